// round 7
// baseline (speedup 1.0000x reference)
#include <cuda_runtime.h>

#define H 64
#define NMAX 50000
#define EMAX 800000

typedef unsigned long long u64;

// ---- static scratch (no allocations allowed) ----
__device__ float g_h[NMAX * H];     // encoder output
__device__ float g_hw[NMAX * H];    // (h @ W[l]) * dinv[node]  (pre-scaled)
__device__ float g_aggA[NMAX * H];  // ping
__device__ float g_aggB[NMAX * H];  // pong
__device__ float g_dinv[NMAX];
__device__ int   g_cnt[NMAX];       // in-degree (excl self-loop); self-clearing
__device__ int   g_off[NMAX + 1];   // CSR row offsets (by dst)
__device__ int   g_cur[NMAX];       // fill cursors
__device__ int   g_csr[EMAX];       // src per edge (CSR by dst)

__device__ __forceinline__ float* buf_ptr(int s) {
    return (s == 0) ? g_h : (s == 1) ? g_aggA : g_aggB;
}

// packed f32x2 helpers
__device__ __forceinline__ void ffma2(u64& d, u64 a, u64 b) {
    asm("fma.rn.f32x2 %0, %1, %2, %3;" : "=l"(d) : "l"(a), "l"(b), "l"(d));
}
__device__ __forceinline__ u64 pack2(float v) {
    u64 r; unsigned u = __float_as_uint(v);
    asm("mov.b64 %0, {%1, %1};" : "=l"(r) : "r"(u));
    return r;
}
union F4U2 { float4 f; u64 u[2]; };

// ---------------- encoder: h = relu(x @ W_enc + b_enc) ----------------
__global__ void __launch_bounds__(256) encoder_k(
    const float* __restrict__ x, const float* __restrict__ W,
    const float* __restrict__ b, int N)
{
    __shared__ float sW[5 * 64];
    __shared__ float sb[64];
    int t = threadIdx.x;
    for (int i = t; i < 320; i += 256) sW[i] = W[i];
    if (t < 64) sb[t] = b[t];
    __syncthreads();

    int gid = blockIdx.x * 256 + t;
    if (gid >= N * 16) return;
    int i = gid >> 4;
    int c = (gid & 15) * 4;

    float xv[5];
#pragma unroll
    for (int f = 0; f < 5; f++) xv[f] = x[i * 5 + f];

    float a0 = sb[c], a1 = sb[c + 1], a2 = sb[c + 2], a3 = sb[c + 3];
#pragma unroll
    for (int f = 0; f < 5; f++) {
        const float* wr = &sW[f * 64 + c];
        a0 += xv[f] * wr[0];
        a1 += xv[f] * wr[1];
        a2 += xv[f] * wr[2];
        a3 += xv[f] * wr[3];
    }
    float4 o;
    o.x = fmaxf(a0, 0.f); o.y = fmaxf(a1, 0.f);
    o.z = fmaxf(a2, 0.f); o.w = fmaxf(a3, 0.f);
    *(float4*)&g_h[i * 64 + c] = o;
}

// ---------------- degree histogram ----------------
__global__ void deg_count_k(const int* __restrict__ dst, int E) {
    int e = blockIdx.x * blockDim.x + threadIdx.x;
    if (e < E) atomicAdd(&g_cnt[dst[e]], 1);
}

// ------- one-pass coarsened scan + dinv + cursor init; self-clears g_cnt ----
__global__ void __launch_bounds__(1024) scan_dinv_k(int N) {
    __shared__ int sWarp[32];
    int tid = threadIdx.x;
    int lane = tid & 31, w = tid >> 5;
    int C = (N + 1023) >> 10;
    int base = tid * C;

    int s = 0;
    for (int c = 0; c < C; c++) {
        int i = base + c;
        if (i < N) s += g_cnt[i];
    }
    int x = s;
#pragma unroll
    for (int o = 1; o < 32; o <<= 1) {
        int y = __shfl_up_sync(0xffffffffu, x, o);
        if (lane >= o) x += y;
    }
    if (lane == 31) sWarp[w] = x;
    __syncthreads();
    if (w == 0) {
        int v = sWarp[lane];
#pragma unroll
        for (int o = 1; o < 32; o <<= 1) {
            int y = __shfl_up_sync(0xffffffffu, v, o);
            if (lane >= o) v += y;
        }
        sWarp[lane] = v;
    }
    __syncthreads();
    int pref = x - s + ((w > 0) ? sWarp[w - 1] : 0);
    if (tid == 0) g_off[N] = sWarp[31];

    for (int c = 0; c < C; c++) {
        int i = base + c;
        if (i < N) {
            int cnt = g_cnt[i];
            g_cnt[i] = 0;
            g_off[i] = pref;
            g_cur[i] = pref;
            g_dinv[i] = rsqrtf(1.0f + (float)cnt);
            pref += cnt;
        }
    }
}

// ---------------- CSR fill (src only) ----------------
__global__ void csr_fill_k(const int* __restrict__ src,
                           const int* __restrict__ dst, int E) {
    int e = blockIdx.x * blockDim.x + threadIdx.x;
    if (e >= E) return;
    int s = src[e];
    int c = dst[e];
    int pos = atomicAdd(&g_cur[c], 1);
    g_csr[pos] = s;
}

// ---------------- GEMM: hw = (preop(in) @ W) * dinv[node] ----------------
// 128 threads, 64-node tile; thread = 2 nodes x 16 cols, f32x2 packed math
__global__ void __launch_bounds__(128) gemm_k(
    int in_sel, const float* __restrict__ W,
    const float* __restrict__ preb, int hasPre, int N)
{
    __shared__ float sW[64 * 64];
    __shared__ float sIn[64 * 65];

    const float* __restrict__ in = buf_ptr(in_sel);

    int t = threadIdx.x;
    int i0 = blockIdx.x * 64;

    {
        const float4* Wv = (const float4*)W;
        float4* sWv = (float4*)sW;
#pragma unroll
        for (int r = 0; r < 8; r++) sWv[t + r * 128] = Wv[t + r * 128];
    }
#pragma unroll
    for (int r = 0; r < 8; r++) {
        int lin = t + r * 128;
        int n = lin >> 4;
        int c4 = (lin & 15) * 4;
        int i = i0 + n;
        float4 v = make_float4(0.f, 0.f, 0.f, 0.f);
        if (i < N) v = *(const float4*)&in[i * 64 + c4];
        if (hasPre) {
            v.x = fmaxf(v.x + preb[c4 + 0], 0.f);
            v.y = fmaxf(v.y + preb[c4 + 1], 0.f);
            v.z = fmaxf(v.z + preb[c4 + 2], 0.f);
            v.w = fmaxf(v.w + preb[c4 + 3], 0.f);
        }
        float* s = &sIn[n * 65 + c4];
        s[0] = v.x; s[1] = v.y; s[2] = v.z; s[3] = v.w;
    }
    __syncthreads();

    int n2 = t >> 2;
    int q  = t & 3;
    int na = 2 * n2, nb = na + 1;

    u64 acc0[8], acc1[8];    // 8 col-pairs per node
#pragma unroll
    for (int j = 0; j < 8; j++) { acc0[j] = 0ull; acc1[j] = 0ull; }

#pragma unroll 8
    for (int k = 0; k < 64; k++) {
        float h0 = sIn[na * 65 + k];
        float h1 = sIn[nb * 65 + k];
        u64 h0p = pack2(h0);
        u64 h1p = pack2(h1);
        const float4* wp = (const float4*)&sW[k * 64 + q * 16];
        F4U2 w0, w1, w2, w3;
        w0.f = wp[0]; w1.f = wp[1]; w2.f = wp[2]; w3.f = wp[3];
        ffma2(acc0[0], h0p, w0.u[0]); ffma2(acc0[1], h0p, w0.u[1]);
        ffma2(acc0[2], h0p, w1.u[0]); ffma2(acc0[3], h0p, w1.u[1]);
        ffma2(acc0[4], h0p, w2.u[0]); ffma2(acc0[5], h0p, w2.u[1]);
        ffma2(acc0[6], h0p, w3.u[0]); ffma2(acc0[7], h0p, w3.u[1]);
        ffma2(acc1[0], h1p, w0.u[0]); ffma2(acc1[1], h1p, w0.u[1]);
        ffma2(acc1[2], h1p, w1.u[0]); ffma2(acc1[3], h1p, w1.u[1]);
        ffma2(acc1[4], h1p, w2.u[0]); ffma2(acc1[5], h1p, w2.u[1]);
        ffma2(acc1[6], h1p, w3.u[0]); ffma2(acc1[7], h1p, w3.u[1]);
    }

    int ia = i0 + na, ib = i0 + nb;
    if (ia < N) {
        float da = g_dinv[ia];
        float* p = &g_hw[ia * 64 + q * 16];
#pragma unroll
        for (int r = 0; r < 4; r++) {
            F4U2 o; o.u[0] = acc0[2*r]; o.u[1] = acc0[2*r+1];
            o.f.x *= da; o.f.y *= da; o.f.z *= da; o.f.w *= da;
            *(float4*)&p[r * 4] = o.f;
        }
    }
    if (ib < N) {
        float db = g_dinv[ib];
        float* p = &g_hw[ib * 64 + q * 16];
#pragma unroll
        for (int r = 0; r < 4; r++) {
            F4U2 o; o.u[0] = acc1[2*r]; o.u[1] = acc1[2*r+1];
            o.f.x *= db; o.f.y *= db; o.f.z *= db; o.f.w *= db;
            *(float4*)&p[r * 4] = o.f;
        }
    }
}

// ------- pull aggregation: agg_i = dinv_i*(hws_i + sum hws[src]); pipelined --
__global__ void __launch_bounds__(256) aggregate_k(int agg_sel, int N)
{
    int idx = blockIdx.x * 256 + threadIdx.x;
    int i = idx >> 4;
    if (i >= N) return;
    int c4 = (idx & 15) * 4;

    float4 acc = *(const float4*)&g_hw[i * 64 + c4];   // self term

    int j = g_off[i];
    int end = g_off[i + 1];

    int s[8];
    if (j + 8 <= end) {
#pragma unroll
        for (int g = 0; g < 8; g++) s[g] = g_csr[j + g];
    }
    while (j + 8 <= end) {
        // issue gathers for current batch
        float4 v0 = __ldcg((const float4*)&g_hw[s[0] * 64 + c4]);
        float4 v1 = __ldcg((const float4*)&g_hw[s[1] * 64 + c4]);
        float4 v2 = __ldcg((const float4*)&g_hw[s[2] * 64 + c4]);
        float4 v3 = __ldcg((const float4*)&g_hw[s[3] * 64 + c4]);
        float4 v4 = __ldcg((const float4*)&g_hw[s[4] * 64 + c4]);
        float4 v5 = __ldcg((const float4*)&g_hw[s[5] * 64 + c4]);
        float4 v6 = __ldcg((const float4*)&g_hw[s[6] * 64 + c4]);
        float4 v7 = __ldcg((const float4*)&g_hw[s[7] * 64 + c4]);
        // prefetch next batch indices (overlaps with gathers in flight)
        int jn = j + 8;
        bool more = (jn + 8 <= end);
        int sn[8];
#pragma unroll
        for (int g = 0; g < 8; g++) sn[g] = more ? g_csr[jn + g] : 0;
        // accumulate
        acc.x += ((v0.x + v1.x) + (v2.x + v3.x)) + ((v4.x + v5.x) + (v6.x + v7.x));
        acc.y += ((v0.y + v1.y) + (v2.y + v3.y)) + ((v4.y + v5.y) + (v6.y + v7.y));
        acc.z += ((v0.z + v1.z) + (v2.z + v3.z)) + ((v4.z + v5.z) + (v6.z + v7.z));
        acc.w += ((v0.w + v1.w) + (v2.w + v3.w)) + ((v4.w + v5.w) + (v6.w + v7.w));
#pragma unroll
        for (int g = 0; g < 8; g++) s[g] = sn[g];
        j = jn;
    }
    if (j + 4 <= end) {
        int s0 = g_csr[j + 0], s1 = g_csr[j + 1], s2 = g_csr[j + 2], s3 = g_csr[j + 3];
        float4 v0 = __ldcg((const float4*)&g_hw[s0 * 64 + c4]);
        float4 v1 = __ldcg((const float4*)&g_hw[s1 * 64 + c4]);
        float4 v2 = __ldcg((const float4*)&g_hw[s2 * 64 + c4]);
        float4 v3 = __ldcg((const float4*)&g_hw[s3 * 64 + c4]);
        acc.x += (v0.x + v1.x) + (v2.x + v3.x);
        acc.y += (v0.y + v1.y) + (v2.y + v3.y);
        acc.z += (v0.z + v1.z) + (v2.z + v3.z);
        acc.w += (v0.w + v1.w) + (v2.w + v3.w);
        j += 4;
    }
    if (j + 2 <= end) {
        int s0 = g_csr[j], s1 = g_csr[j + 1];
        float4 v0 = __ldcg((const float4*)&g_hw[s0 * 64 + c4]);
        float4 v1 = __ldcg((const float4*)&g_hw[s1 * 64 + c4]);
        acc.x += v0.x + v1.x; acc.y += v0.y + v1.y;
        acc.z += v0.z + v1.z; acc.w += v0.w + v1.w;
        j += 2;
    }
    if (j < end) {
        int s0 = g_csr[j];
        float4 v0 = __ldcg((const float4*)&g_hw[s0 * 64 + c4]);
        acc.x += v0.x; acc.y += v0.y; acc.z += v0.z; acc.w += v0.w;
    }

    float dv = g_dinv[i];
    float* agg = buf_ptr(agg_sel);
    *(float4*)&agg[i * 64 + c4] =
        make_float4(acc.x * dv, acc.y * dv, acc.z * dv, acc.w * dv);
}

// ---------------- heads: demand / inventory (one warp per node) ----------------
__global__ void __launch_bounds__(256) heads_k(
    int in_sel, const float* __restrict__ cb,
    const float* __restrict__ Wd1, const float* __restrict__ bd1,
    const float* __restrict__ Wd2, const float* __restrict__ bd2,
    const float* __restrict__ Wi1, const float* __restrict__ bi1,
    const float* __restrict__ Wi2, const float* __restrict__ bi2,
    float* __restrict__ out, int N)
{
    __shared__ float sWd1[64 * 32];
    __shared__ float sWi1[64 * 32];
    __shared__ float sWd2[32], sWi2[32], sbd1[32], sbi1[32], scb[64];
    __shared__ float sh[8 * 64];

    int t = threadIdx.x;
    {
        const float4* wd = (const float4*)Wd1;
        const float4* wi = (const float4*)Wi1;
        float4* swd = (float4*)sWd1;
        float4* swi = (float4*)sWi1;
        swd[t] = wd[t]; swd[t + 256] = wd[t + 256];
        swi[t] = wi[t]; swi[t + 256] = wi[t + 256];
    }
    if (t < 32) { sWd2[t] = Wd2[t]; sWi2[t] = Wi2[t]; sbd1[t] = bd1[t]; sbi1[t] = bi1[t]; }
    if (t < 64) scb[t] = cb[t];
    __syncthreads();

    const float* in = buf_ptr(in_sel);
    int w = t >> 5, lane = t & 31;
    int i = blockIdx.x * 8 + w;

    if (i < N) {
        float v0 = fmaxf(in[i * 64 + lane]      + scb[lane],      0.f);
        float v1 = fmaxf(in[i * 64 + lane + 32] + scb[lane + 32], 0.f);
        sh[w * 64 + lane] = v0;
        sh[w * 64 + lane + 32] = v1;
    }
    __syncwarp();
    if (i >= N) return;

    float ad = sbd1[lane];
    float ai = sbi1[lane];
#pragma unroll 16
    for (int k = 0; k < 64; k++) {
        float hv = sh[w * 64 + k];
        ad += hv * sWd1[k * 32 + lane];
        ai += hv * sWi1[k * 32 + lane];
    }
    float vd = fmaxf(ad, 0.f) * sWd2[lane];
    float vi = fmaxf(ai, 0.f) * sWi2[lane];
#pragma unroll
    for (int o = 16; o > 0; o >>= 1) {
        vd += __shfl_xor_sync(0xffffffffu, vd, o);
        vi += __shfl_xor_sync(0xffffffffu, vi, o);
    }
    if (lane == 0) {
        out[i]     = vd + bd2[0];
        out[N + i] = vi + bi2[0];
    }
}

// ---------------- launch ----------------
extern "C" void kernel_launch(void* const* d_in, const int* in_sizes, int n_in,
                              void* d_out, int out_size)
{
    const float* x      = (const float*)d_in[0];
    const int*   ei     = (const int*)d_in[1];     // int32 (JAX x64 off)
    const float* W_enc  = (const float*)d_in[2];
    const float* b_enc  = (const float*)d_in[3];
    const float* conv_W = (const float*)d_in[4];   // [3][64][64]
    const float* conv_b = (const float*)d_in[5];   // [3][64]
    const float* W_d1   = (const float*)d_in[6];
    const float* b_d1   = (const float*)d_in[7];
    const float* W_d2   = (const float*)d_in[8];
    const float* b_d2   = (const float*)d_in[9];
    const float* W_i1   = (const float*)d_in[10];
    const float* b_i1   = (const float*)d_in[11];
    const float* W_i2   = (const float*)d_in[12];
    const float* b_i2   = (const float*)d_in[13];
    float* out = (float*)d_out;

    int N = in_sizes[0] / 5;
    int E = in_sizes[1] / 2;
    const int* src = ei;       // edge_index[0] (source)
    const int* dst = ei + E;   // edge_index[1] (target)

    int nbE = (E + 255) / 256;
    int gemmB = (N + 63) / 64;
    int aggB  = (N * 16 + 255) / 256;

    // 0: encoder
    encoder_k<<<(N * 16 + 255) / 256, 256>>>(x, W_enc, b_enc, N);
    // 1: degree histogram (g_cnt cleared by previous scan / zero-init)
    deg_count_k<<<nbE, 256>>>(dst, E);
    // 2: scan + dinv + cursors (+ cnt self-clear)
    scan_dinv_k<<<1, 1024>>>(N);
    // 3: layer0 gemm (ncu slot 3 profiles the new f32x2 gemm)
    gemm_k<<<gemmB, 128>>>(0, conv_W + 0 * 4096, nullptr, 0, N);
    // 4: CSR fill
    csr_fill_k<<<nbE, 256>>>(src, dst, E);
    // 5: layer0 aggregate
    aggregate_k<<<aggB, 256>>>(1, N);
    // 6-7: layer1
    gemm_k<<<gemmB, 128>>>(1, conv_W + 1 * 4096, conv_b + 0 * 64, 1, N);
    aggregate_k<<<aggB, 256>>>(2, N);
    // 8-9: layer2
    gemm_k<<<gemmB, 128>>>(2, conv_W + 2 * 4096, conv_b + 1 * 64, 1, N);
    aggregate_k<<<aggB, 256>>>(1, N);
    // 10: heads
    heads_k<<<(N + 7) / 8, 256>>>(1, conv_b + 2 * 64,
                                  W_d1, b_d1, W_d2, b_d2,
                                  W_i1, b_i1, W_i2, b_i2,
                                  out, N);
}

// round 8
// speedup vs baseline: 1.1450x; 1.1450x over previous
#include <cuda_runtime.h>

#define H 64
#define NMAX 50000
#define EMAX 800000

typedef unsigned long long u64;

// ---- static scratch (no allocations allowed) ----
__device__ float g_h[NMAX * H];     // encoder output
__device__ float g_hw[NMAX * H];    // (h @ W[l]) * dinv[node]  (pre-scaled)
__device__ float g_aggA[NMAX * H];  // ping
__device__ float g_aggB[NMAX * H];  // pong
__device__ float g_dinv[NMAX];
__device__ int   g_cnt[NMAX];       // in-degree; self-cleared by scan
__device__ int   g_off[NMAX + 1];   // CSR row offsets (by dst)
__device__ int   g_cur[NMAX];       // fill cursors
__device__ int   g_csr[EMAX];       // src per edge (CSR by dst)

__device__ __forceinline__ float* buf_ptr(int s) {
    return (s == 0) ? g_h : (s == 1) ? g_aggA : g_aggB;
}

// packed f32x2 helpers
__device__ __forceinline__ void ffma2(u64& d, u64 a, u64 b) {
    asm("fma.rn.f32x2 %0, %1, %2, %3;" : "=l"(d) : "l"(a), "l"(b), "l"(d));
}
__device__ __forceinline__ u64 pack2(float v) {
    u64 r; unsigned u = __float_as_uint(v);
    asm("mov.b64 %0, {%1, %1};" : "=l"(r) : "r"(u));
    return r;
}
union F4U2 { float4 f; u64 u[2]; };

// ============ fused encoder + degree histogram ============
// blocks [0, encB): encoder; blocks [encB, encB+degB): degree count
__global__ void __launch_bounds__(256) enc_deg_k(
    const float* __restrict__ x, const float* __restrict__ W,
    const float* __restrict__ b, const int* __restrict__ dst,
    int N, int E, int encB)
{
    int t = threadIdx.x;
    if ((int)blockIdx.x >= encB) {
        int e = (blockIdx.x - encB) * 256 + t;
        if (e < E) atomicAdd(&g_cnt[dst[e]], 1);
        return;
    }
    __shared__ float sW[5 * 64];
    __shared__ float sb[64];
    for (int i = t; i < 320; i += 256) sW[i] = W[i];
    if (t < 64) sb[t] = b[t];
    __syncthreads();

    int gid = blockIdx.x * 256 + t;
    if (gid >= N * 16) return;
    int i = gid >> 4;
    int c = (gid & 15) * 4;

    float xv[5];
#pragma unroll
    for (int f = 0; f < 5; f++) xv[f] = x[i * 5 + f];

    float a0 = sb[c], a1 = sb[c + 1], a2 = sb[c + 2], a3 = sb[c + 3];
#pragma unroll
    for (int f = 0; f < 5; f++) {
        const float* wr = &sW[f * 64 + c];
        a0 += xv[f] * wr[0];
        a1 += xv[f] * wr[1];
        a2 += xv[f] * wr[2];
        a3 += xv[f] * wr[3];
    }
    float4 o;
    o.x = fmaxf(a0, 0.f); o.y = fmaxf(a1, 0.f);
    o.z = fmaxf(a2, 0.f); o.w = fmaxf(a3, 0.f);
    *(float4*)&g_h[i * 64 + c] = o;
}

// ------- one-pass coarsened scan + dinv + cursor init; self-clears g_cnt ----
__global__ void __launch_bounds__(1024) scan_dinv_k(int N) {
    __shared__ int sWarp[32];
    int tid = threadIdx.x;
    int lane = tid & 31, w = tid >> 5;
    int C = (N + 1023) >> 10;
    int base = tid * C;

    int s = 0;
    for (int c = 0; c < C; c++) {
        int i = base + c;
        if (i < N) s += g_cnt[i];
    }
    int x = s;
#pragma unroll
    for (int o = 1; o < 32; o <<= 1) {
        int y = __shfl_up_sync(0xffffffffu, x, o);
        if (lane >= o) x += y;
    }
    if (lane == 31) sWarp[w] = x;
    __syncthreads();
    if (w == 0) {
        int v = sWarp[lane];
#pragma unroll
        for (int o = 1; o < 32; o <<= 1) {
            int y = __shfl_up_sync(0xffffffffu, v, o);
            if (lane >= o) v += y;
        }
        sWarp[lane] = v;
    }
    __syncthreads();
    int pref = x - s + ((w > 0) ? sWarp[w - 1] : 0);
    if (tid == 0) g_off[N] = sWarp[31];

    for (int c = 0; c < C; c++) {
        int i = base + c;
        if (i < N) {
            int cnt = g_cnt[i];
            g_cnt[i] = 0;
            g_off[i] = pref;
            g_cur[i] = pref;
            g_dinv[i] = rsqrtf(1.0f + (float)cnt);
            pref += cnt;
        }
    }
}

// ============ GEMM body: hw = (preop(in) @ W) * dinv[node] ============
// 128 threads; tile 128 nodes; thread = 4 nodes x 16 cols (f32x2 packed).
// W read via __ldg (16KB, L1-resident); h staged in smem.
__device__ __forceinline__ void gemm_body(
    const float* __restrict__ in, const float* __restrict__ W,
    const float* __restrict__ preb, int hasPre, int N, int bid)
{
    __shared__ float sIn[128 * 65];

    int t = threadIdx.x;
    int i0 = bid * 128;

#pragma unroll
    for (int r = 0; r < 16; r++) {
        int lin = t + r * 128;          // float4 unit 0..2047
        int n = lin >> 4;
        int c4 = (lin & 15) * 4;
        int i = i0 + n;
        float4 v = make_float4(0.f, 0.f, 0.f, 0.f);
        if (i < N) v = *(const float4*)&in[i * 64 + c4];
        if (hasPre) {
            v.x = fmaxf(v.x + preb[c4 + 0], 0.f);
            v.y = fmaxf(v.y + preb[c4 + 1], 0.f);
            v.z = fmaxf(v.z + preb[c4 + 2], 0.f);
            v.w = fmaxf(v.w + preb[c4 + 3], 0.f);
        }
        float* s = &sIn[n * 65 + c4];
        s[0] = v.x; s[1] = v.y; s[2] = v.z; s[3] = v.w;
    }
    __syncthreads();

    int q  = t & 3;          // col quarter (16 cols)
    int g  = t >> 2;         // node group 0..31
    int nb = g * 4;

    u64 acc0[8], acc1[8], acc2[8], acc3[8];
#pragma unroll
    for (int j = 0; j < 8; j++) { acc0[j]=0ull; acc1[j]=0ull; acc2[j]=0ull; acc3[j]=0ull; }

    const float4* __restrict__ Wq = (const float4*)(W + q * 16);

#pragma unroll 4
    for (int k = 0; k < 64; k++) {
        u64 h0 = pack2(sIn[(nb + 0) * 65 + k]);
        u64 h1 = pack2(sIn[(nb + 1) * 65 + k]);
        u64 h2 = pack2(sIn[(nb + 2) * 65 + k]);
        u64 h3 = pack2(sIn[(nb + 3) * 65 + k]);
        const float4* wp = Wq + k * 16;   // k*64 floats = k*16 float4
        F4U2 w0, w1, w2, w3;
        w0.f = __ldg(wp); w1.f = __ldg(wp + 1); w2.f = __ldg(wp + 2); w3.f = __ldg(wp + 3);
        ffma2(acc0[0], h0, w0.u[0]); ffma2(acc0[1], h0, w0.u[1]);
        ffma2(acc0[2], h0, w1.u[0]); ffma2(acc0[3], h0, w1.u[1]);
        ffma2(acc0[4], h0, w2.u[0]); ffma2(acc0[5], h0, w2.u[1]);
        ffma2(acc0[6], h0, w3.u[0]); ffma2(acc0[7], h0, w3.u[1]);
        ffma2(acc1[0], h1, w0.u[0]); ffma2(acc1[1], h1, w0.u[1]);
        ffma2(acc1[2], h1, w1.u[0]); ffma2(acc1[3], h1, w1.u[1]);
        ffma2(acc1[4], h1, w2.u[0]); ffma2(acc1[5], h1, w2.u[1]);
        ffma2(acc1[6], h1, w3.u[0]); ffma2(acc1[7], h1, w3.u[1]);
        ffma2(acc2[0], h2, w0.u[0]); ffma2(acc2[1], h2, w0.u[1]);
        ffma2(acc2[2], h2, w1.u[0]); ffma2(acc2[3], h2, w1.u[1]);
        ffma2(acc2[4], h2, w2.u[0]); ffma2(acc2[5], h2, w2.u[1]);
        ffma2(acc2[6], h2, w3.u[0]); ffma2(acc2[7], h2, w3.u[1]);
        ffma2(acc3[0], h3, w0.u[0]); ffma2(acc3[1], h3, w0.u[1]);
        ffma2(acc3[2], h3, w1.u[0]); ffma2(acc3[3], h3, w1.u[1]);
        ffma2(acc3[4], h3, w2.u[0]); ffma2(acc3[5], h3, w2.u[1]);
        ffma2(acc3[6], h3, w3.u[0]); ffma2(acc3[7], h3, w3.u[1]);
    }

    u64* accs[4] = {acc0, acc1, acc2, acc3};
#pragma unroll
    for (int m = 0; m < 4; m++) {
        int i = i0 + nb + m;
        if (i < N) {
            float da = g_dinv[i];
            float* p = &g_hw[i * 64 + q * 16];
#pragma unroll
            for (int r = 0; r < 4; r++) {
                F4U2 o; o.u[0] = accs[m][2*r]; o.u[1] = accs[m][2*r+1];
                o.f.x *= da; o.f.y *= da; o.f.z *= da; o.f.w *= da;
                *(float4*)&p[r * 4] = o.f;
            }
        }
    }
}

__global__ void __launch_bounds__(128) gemm_k(
    int in_sel, const float* __restrict__ W,
    const float* __restrict__ preb, int hasPre, int N)
{
    gemm_body(buf_ptr(in_sel), W, preb, hasPre, N, blockIdx.x);
}

// ============ fused gemm(layer0) + CSR fill ============
__global__ void __launch_bounds__(128) gemm_csr_k(
    const float* __restrict__ W,
    const int* __restrict__ src, const int* __restrict__ dst,
    int N, int E, int gemmB)
{
    if ((int)blockIdx.x >= gemmB) {
        int e = (blockIdx.x - gemmB) * 128 + threadIdx.x;
        if (e < E) {
            int s = src[e];
            int c = dst[e];
            int pos = atomicAdd(&g_cur[c], 1);
            g_csr[pos] = s;
        }
        return;
    }
    gemm_body(g_h, W, nullptr, 0, N, blockIdx.x);
}

// ------- pull aggregation: agg_i = dinv_i*(hws_i + sum hws[src]) ------------
__global__ void __launch_bounds__(256) aggregate_k(int agg_sel, int N)
{
    int idx = blockIdx.x * 256 + threadIdx.x;
    int i = idx >> 4;
    if (i >= N) return;
    int c4 = (idx & 15) * 4;

    float4 acc = *(const float4*)&g_hw[i * 64 + c4];   // self term

    int j = g_off[i];
    int end = g_off[i + 1];

    while (j + 8 <= end) {
        int s0 = g_csr[j + 0], s1 = g_csr[j + 1], s2 = g_csr[j + 2], s3 = g_csr[j + 3];
        int s4 = g_csr[j + 4], s5 = g_csr[j + 5], s6 = g_csr[j + 6], s7 = g_csr[j + 7];
        float4 v0 = __ldcg((const float4*)&g_hw[s0 * 64 + c4]);
        float4 v1 = __ldcg((const float4*)&g_hw[s1 * 64 + c4]);
        float4 v2 = __ldcg((const float4*)&g_hw[s2 * 64 + c4]);
        float4 v3 = __ldcg((const float4*)&g_hw[s3 * 64 + c4]);
        float4 v4 = __ldcg((const float4*)&g_hw[s4 * 64 + c4]);
        float4 v5 = __ldcg((const float4*)&g_hw[s5 * 64 + c4]);
        float4 v6 = __ldcg((const float4*)&g_hw[s6 * 64 + c4]);
        float4 v7 = __ldcg((const float4*)&g_hw[s7 * 64 + c4]);
        acc.x += ((v0.x + v1.x) + (v2.x + v3.x)) + ((v4.x + v5.x) + (v6.x + v7.x));
        acc.y += ((v0.y + v1.y) + (v2.y + v3.y)) + ((v4.y + v5.y) + (v6.y + v7.y));
        acc.z += ((v0.z + v1.z) + (v2.z + v3.z)) + ((v4.z + v5.z) + (v6.z + v7.z));
        acc.w += ((v0.w + v1.w) + (v2.w + v3.w)) + ((v4.w + v5.w) + (v6.w + v7.w));
        j += 8;
    }
    if (j + 4 <= end) {
        int s0 = g_csr[j + 0], s1 = g_csr[j + 1], s2 = g_csr[j + 2], s3 = g_csr[j + 3];
        float4 v0 = __ldcg((const float4*)&g_hw[s0 * 64 + c4]);
        float4 v1 = __ldcg((const float4*)&g_hw[s1 * 64 + c4]);
        float4 v2 = __ldcg((const float4*)&g_hw[s2 * 64 + c4]);
        float4 v3 = __ldcg((const float4*)&g_hw[s3 * 64 + c4]);
        acc.x += (v0.x + v1.x) + (v2.x + v3.x);
        acc.y += (v0.y + v1.y) + (v2.y + v3.y);
        acc.z += (v0.z + v1.z) + (v2.z + v3.z);
        acc.w += (v0.w + v1.w) + (v2.w + v3.w);
        j += 4;
    }
    if (j + 2 <= end) {
        int s0 = g_csr[j], s1 = g_csr[j + 1];
        float4 v0 = __ldcg((const float4*)&g_hw[s0 * 64 + c4]);
        float4 v1 = __ldcg((const float4*)&g_hw[s1 * 64 + c4]);
        acc.x += v0.x + v1.x; acc.y += v0.y + v1.y;
        acc.z += v0.z + v1.z; acc.w += v0.w + v1.w;
        j += 2;
    }
    if (j < end) {
        int s0 = g_csr[j];
        float4 v0 = __ldcg((const float4*)&g_hw[s0 * 64 + c4]);
        acc.x += v0.x; acc.y += v0.y; acc.z += v0.z; acc.w += v0.w;
    }

    float dv = g_dinv[i];
    float* agg = buf_ptr(agg_sel);
    *(float4*)&agg[i * 64 + c4] =
        make_float4(acc.x * dv, acc.y * dv, acc.z * dv, acc.w * dv);
}

// ---------------- heads: demand / inventory (one warp per node) ----------------
__global__ void __launch_bounds__(256) heads_k(
    int in_sel, const float* __restrict__ cb,
    const float* __restrict__ Wd1, const float* __restrict__ bd1,
    const float* __restrict__ Wd2, const float* __restrict__ bd2,
    const float* __restrict__ Wi1, const float* __restrict__ bi1,
    const float* __restrict__ Wi2, const float* __restrict__ bi2,
    float* __restrict__ out, int N)
{
    __shared__ float sWd1[64 * 32];
    __shared__ float sWi1[64 * 32];
    __shared__ float sWd2[32], sWi2[32], sbd1[32], sbi1[32], scb[64];
    __shared__ float sh[8 * 64];

    int t = threadIdx.x;
    {
        const float4* wd = (const float4*)Wd1;
        const float4* wi = (const float4*)Wi1;
        float4* swd = (float4*)sWd1;
        float4* swi = (float4*)sWi1;
        swd[t] = wd[t]; swd[t + 256] = wd[t + 256];
        swi[t] = wi[t]; swi[t + 256] = wi[t + 256];
    }
    if (t < 32) { sWd2[t] = Wd2[t]; sWi2[t] = Wi2[t]; sbd1[t] = bd1[t]; sbi1[t] = bi1[t]; }
    if (t < 64) scb[t] = cb[t];
    __syncthreads();

    const float* in = buf_ptr(in_sel);
    int w = t >> 5, lane = t & 31;
    int i = blockIdx.x * 8 + w;

    if (i < N) {
        float v0 = fmaxf(in[i * 64 + lane]      + scb[lane],      0.f);
        float v1 = fmaxf(in[i * 64 + lane + 32] + scb[lane + 32], 0.f);
        sh[w * 64 + lane] = v0;
        sh[w * 64 + lane + 32] = v1;
    }
    __syncwarp();
    if (i >= N) return;

    float ad = sbd1[lane];
    float ai = sbi1[lane];
#pragma unroll 16
    for (int k = 0; k < 64; k++) {
        float hv = sh[w * 64 + k];
        ad += hv * sWd1[k * 32 + lane];
        ai += hv * sWi1[k * 32 + lane];
    }
    float vd = fmaxf(ad, 0.f) * sWd2[lane];
    float vi = fmaxf(ai, 0.f) * sWi2[lane];
#pragma unroll
    for (int o = 16; o > 0; o >>= 1) {
        vd += __shfl_xor_sync(0xffffffffu, vd, o);
        vi += __shfl_xor_sync(0xffffffffu, vi, o);
    }
    if (lane == 0) {
        out[i]     = vd + bd2[0];
        out[N + i] = vi + bi2[0];
    }
}

// ---------------- launch ----------------
extern "C" void kernel_launch(void* const* d_in, const int* in_sizes, int n_in,
                              void* d_out, int out_size)
{
    const float* x      = (const float*)d_in[0];
    const int*   ei     = (const int*)d_in[1];     // int32 (JAX x64 off)
    const float* W_enc  = (const float*)d_in[2];
    const float* b_enc  = (const float*)d_in[3];
    const float* conv_W = (const float*)d_in[4];   // [3][64][64]
    const float* conv_b = (const float*)d_in[5];   // [3][64]
    const float* W_d1   = (const float*)d_in[6];
    const float* b_d1   = (const float*)d_in[7];
    const float* W_d2   = (const float*)d_in[8];
    const float* b_d2   = (const float*)d_in[9];
    const float* W_i1   = (const float*)d_in[10];
    const float* b_i1   = (const float*)d_in[11];
    const float* W_i2   = (const float*)d_in[12];
    const float* b_i2   = (const float*)d_in[13];
    float* out = (float*)d_out;

    int N = in_sizes[0] / 5;
    int E = in_sizes[1] / 2;
    const int* src = ei;       // edge_index[0] (source)
    const int* dst = ei + E;   // edge_index[1] (target)

    int encB  = (N * 16 + 255) / 256;
    int degB  = (E + 255) / 256;
    int gemmB = (N + 127) / 128;
    int csrB  = (E + 127) / 128;
    int aggB  = (N * 16 + 255) / 256;

    // 0: encoder + degree histogram (fused co-grid)
    enc_deg_k<<<encB + degB, 256>>>(x, W_enc, b_enc, dst, N, E, encB);
    // 1: scan + dinv + cursors (+ cnt self-clear)
    scan_dinv_k<<<1, 1024>>>(N);
    // 2: layer0 gemm + CSR fill (fused co-grid)
    gemm_csr_k<<<gemmB + csrB, 128>>>(conv_W + 0 * 4096, src, dst, N, E, gemmB);
    // 3: layer0 aggregate  <-- ncu slot 3 profiles THIS now
    aggregate_k<<<aggB, 256>>>(1, N);
    // 4-5: layer1
    gemm_k<<<gemmB, 128>>>(1, conv_W + 1 * 4096, conv_b + 0 * 64, 1, N);
    aggregate_k<<<aggB, 256>>>(2, N);
    // 6-7: layer2
    gemm_k<<<gemmB, 128>>>(2, conv_W + 2 * 4096, conv_b + 1 * 64, 1, N);
    aggregate_k<<<aggB, 256>>>(1, N);
    // 8: heads
    heads_k<<<(N + 7) / 8, 256>>>(1, conv_b + 2 * 64,
                                  W_d1, b_d1, W_d2, b_d2,
                                  W_i1, b_i1, W_i2, b_i2,
                                  out, N);
}